// round 6
// baseline (speedup 1.0000x reference)
#include <cuda_runtime.h>
#include <cuda_bf16.h>
#include <math.h>
#include <stdint.h>

// Problem constants
#define BB   2
#define NN   4096
#define BNP  (BB*NN)        // 8192 rows
#define DIMV 256
#define KNNV 16
#define M2   (BNP*KNNV)     // 131072 rows for per-neighbor tensors

typedef __nv_bfloat16 bf16;
typedef __nv_bfloat162 bf162;

// -------------------- scratch (no allocations allowed) --------------------
__device__ float g_qa [BNP*DIMV];          // x @ (wq@aw1)
__device__ float g_ka [BNP*DIMV];          // x @ (wk@aw1)
__device__ bf16  g_v  [BNP*DIMV];
__device__ bf16  g_agg[BNP*DIMV];
__device__ int   g_idx[M2];
__device__ bf16  g_h  [(size_t)M2*DIMV];   // relu(rel@pw1+pb1)
__device__ bf16  g_pe [(size_t)M2*DIMV];   // h@pw2+pb2
__device__ bf16  g_h2 [(size_t)M2*DIMV];   // relu(h@Wpa + qa - ka + bpa)
__device__ bf16  g_a2 [(size_t)M2*DIMV];   // h2@aw2+ab2
__device__ bf16  g_wt [7*DIMV*DIMV];       // transposed bf16 weights [n][k]
__device__ bf16  g_xb [BNP*DIMV];          // bf16 x
__device__ float g_bpa[DIMV];              // pb2@aw1 + ab1

// weight slots in g_wt
#define WT_WV  0
#define WT_PW2 1
#define WT_AW2 2
#define WT_FW  3
#define WT_WQA 4
#define WT_WKA 5
#define WT_WPA 6

// ==================== bf16 tensor-core GEMM ====================
// CTA tile 128x128, BK=64, 8 warps (2x4), mma.m16n8k16.bf16, ldmatrix frags.
// A: M x 256 bf16 row-major.  Bt: 256 x 256 bf16 TRANSPOSED [n][k].
// Dual mode: grid.x=4, CTAs 0-1 use (Bt0,...), 2-3 use (Bt1,...).

#define BKV   64
#define ASTR  72                    // bf16 elems per smem row (144B)
#define TBUF  (128*ASTR)            // one tile buffer (bf16 elems)
#define GEMM_SMEM_BYTES (4*TBUF*2)  // A x2 + B x2 = 73728 B

// epilogue flags
#define F_RELU 1
#define F_OBF  2
#define F_QK   4

__device__ __forceinline__ void cp16b(bf16* s, const bf16* g) {
    uint32_t sa = (uint32_t)__cvta_generic_to_shared(s);
    asm volatile("cp.async.cg.shared.global [%0], [%1], 16;\n" :: "r"(sa), "l"(g));
}

#define LDSM4(r0, r1, r2, r3, addr)                                          \
    asm volatile("ldmatrix.sync.aligned.m8n8.x4.shared.b16 {%0,%1,%2,%3}, [%4];" \
                 : "=r"(r0), "=r"(r1), "=r"(r2), "=r"(r3) : "r"(addr))

__global__ __launch_bounds__(256)
void gemm_bf16_kernel(const bf16* __restrict__ A,
                      const bf16* __restrict__ Bt0, const bf16* __restrict__ Bt1,
                      const float* __restrict__ bias0, const float* __restrict__ bias1,
                      const float* __restrict__ qa, const float* __restrict__ ka,
                      const float* __restrict__ resid,
                      void* __restrict__ out0, void* __restrict__ out1,
                      int M, int flags0, int flags1)
{
    extern __shared__ bf16 smem[];
    bf16* As = smem;              // [2][128][ASTR]
    bf16* Bs = smem + 2 * TBUF;   // [2][128][ASTR]

    const int tid  = threadIdx.x;
    const int lane = tid & 31;
    const int warp = tid >> 5;
    const int wm   = warp >> 2;       // 0..1  -> 64 rows
    const int wn   = warp & 3;        // 0..3  -> 32 cols
    const int bm   = blockIdx.y * 128;

    int sub, bn;
    if (Bt1) { sub = blockIdx.x >> 1; bn = (blockIdx.x & 1) * 128; }
    else     { sub = 0;               bn = blockIdx.x * 128; }
    const bf16*  Bt    = sub ? Bt1    : Bt0;
    const float* bias  = sub ? bias1  : bias0;
    void*        Cout  = sub ? out1   : out0;
    const int    flags = sub ? flags1 : flags0;

    const int g  = lane >> 2;         // groupID 0..7
    const int tg = lane & 3;          // thread-in-group 0..3

    float acc[4][4][4];
#pragma unroll
    for (int i = 0; i < 4; ++i)
#pragma unroll
        for (int j = 0; j < 4; ++j)
#pragma unroll
            for (int c = 0; c < 4; ++c) acc[i][j][c] = 0.f;

    auto load_tile = [&](int buf, int k0) {
#pragma unroll
        for (int u = 0; u < 4; ++u) {
            int idx = tid + u * 256;          // 0..1023
            int row = idx >> 3;               // 0..127
            int c8  = (idx & 7) * 8;          // 0..56 (bf16 elems)
            cp16b(&As[buf * TBUF + row * ASTR + c8],
                  A + (size_t)(bm + row) * 256 + k0 + c8);
        }
#pragma unroll
        for (int u = 0; u < 4; ++u) {
            int idx = tid + u * 256;
            int row = idx >> 3;               // n index 0..127
            int c8  = (idx & 7) * 8;
            cp16b(&Bs[buf * TBUF + row * ASTR + c8],
                  Bt + (size_t)(bn + row) * 256 + k0 + c8);
        }
        asm volatile("cp.async.commit_group;\n");
    };

    // ldmatrix per-lane base addresses
    const int sel  = lane >> 3;       // 0..3
    const int rsub = lane & 7;
    const uint32_t sA = (uint32_t)__cvta_generic_to_shared(As);
    const uint32_t sB = (uint32_t)__cvta_generic_to_shared(Bs);
    const uint32_t aBase =
        sA + (uint32_t)(((wm * 64 + rsub + (sel & 1) * 8) * ASTR + (sel >> 1) * 8) * 2);
    const uint32_t bBase =
        sB + (uint32_t)(((wn * 32 + rsub + (sel & 1) * 8) * ASTR + (sel >> 1) * 8) * 2);

    load_tile(0, 0);

    for (int t = 0; t < 4; ++t) {
        const int buf = t & 1;
        if (t < 3) {
            load_tile(buf ^ 1, (t + 1) * BKV);
            asm volatile("cp.async.wait_group 1;\n");
        } else {
            asm volatile("cp.async.wait_group 0;\n");
        }
        __syncthreads();

        const uint32_t aT = aBase + (uint32_t)buf * (TBUF * 2);
        const uint32_t bT = bBase + (uint32_t)buf * (TBUF * 2);

#pragma unroll
        for (int ks = 0; ks < 4; ++ks) {
            const uint32_t koff = ks * 16 * 2;
            uint32_t af[4][4], bfr[4][2];
#pragma unroll
            for (int mt = 0; mt < 4; ++mt) {
                LDSM4(af[mt][0], af[mt][1], af[mt][2], af[mt][3],
                      aT + (uint32_t)(mt * 16 * ASTR * 2) + koff);
            }
#pragma unroll
            for (int p = 0; p < 2; ++p) {
                LDSM4(bfr[2 * p][0], bfr[2 * p + 1][0], bfr[2 * p][1], bfr[2 * p + 1][1],
                      bT + (uint32_t)(p * 16 * ASTR * 2) + koff);
            }
#pragma unroll
            for (int mt = 0; mt < 4; ++mt)
#pragma unroll
                for (int nt = 0; nt < 4; ++nt) {
                    asm volatile(
                        "mma.sync.aligned.m16n8k16.row.col.f32.bf16.bf16.f32 "
                        "{%0,%1,%2,%3}, {%4,%5,%6,%7}, {%8,%9}, {%0,%1,%2,%3};\n"
                        : "+f"(acc[mt][nt][0]), "+f"(acc[mt][nt][1]),
                          "+f"(acc[mt][nt][2]), "+f"(acc[mt][nt][3])
                        : "r"(af[mt][0]), "r"(af[mt][1]), "r"(af[mt][2]), "r"(af[mt][3]),
                          "r"(bfr[nt][0]), "r"(bfr[nt][1]));
                }
        }
        __syncthreads();
    }

    // epilogue
    const bool doRelu = flags & F_RELU;
    const bool obf    = flags & F_OBF;
    const bool doQK   = flags & F_QK;
#pragma unroll
    for (int mt = 0; mt < 4; ++mt) {
#pragma unroll
        for (int nt = 0; nt < 4; ++nt) {
            int row0 = bm + wm * 64 + mt * 16 + g;
            int col0 = bn + wn * 32 + nt * 8 + 2 * tg;
#pragma unroll
            for (int h = 0; h < 2; ++h) {
                int row = row0 + h * 8;
                float c0 = acc[mt][nt][2 * h];
                float c1 = acc[mt][nt][2 * h + 1];
                if (bias) { c0 += bias[col0]; c1 += bias[col0 + 1]; }
                if (doQK) {
                    int n = row >> 4;
                    int r = g_idx[row];
                    float2 qv = *(const float2*)(qa + (size_t)n * 256 + col0);
                    float2 kv = *(const float2*)(ka + (size_t)r * 256 + col0);
                    c0 += qv.x - kv.x;
                    c1 += qv.y - kv.y;
                }
                if (doRelu) { c0 = fmaxf(c0, 0.f); c1 = fmaxf(c1, 0.f); }
                if (obf) {
                    *(bf162*)((bf16*)Cout + (size_t)row * 256 + col0) =
                        __floats2bfloat162_rn(c0, c1);
                } else {
                    if (resid) {
                        c0 += resid[(size_t)row * 256 + col0];
                        c1 += resid[(size_t)row * 256 + col0 + 1];
                    }
                    *(float2*)((float*)Cout + (size_t)row * 256 + col0) =
                        make_float2(c0, c1);
                }
            }
        }
    }
}

// -------------------- prep: convert / transpose / fold --------------------
struct WSrcs { const float* p[4]; };   // wv, pw2, aw2, fw

__global__ __launch_bounds__(256)
void conv_weights_kernel(WSrcs ws)
{
    const int sel = blockIdx.x >> 8;      // 0..3
    const int n   = blockIdx.x & 255;
    const int k   = threadIdx.x;
    g_wt[(size_t)sel * 65536 + n * 256 + k] =
        __float2bfloat16_rn(ws.p[sel][k * 256 + n]);
}

// Wqa = wq@aw1, Wka = wk@aw1, Wpa = pw2@aw1 (stored transposed, bf16),
// bpa = pb2@aw1 + ab1 (fp32)
__global__ __launch_bounds__(256)
void fold_kernel(const float* __restrict__ wq, const float* __restrict__ wk,
                 const float* __restrict__ pw2, const float* __restrict__ aw1,
                 const float* __restrict__ pb2, const float* __restrict__ ab1)
{
    const int b = blockIdx.x;
    const int j = threadIdx.x;
    if (b < 768) {
        const int sel = b >> 8;
        const int i   = b & 255;
        const float* src = (sel == 0) ? wq : (sel == 1) ? wk : pw2;
        float s = 0.f;
        for (int d = 0; d < 256; ++d)
            s = fmaf(src[i * 256 + d], aw1[d * 256 + j], s);
        g_wt[(size_t)(WT_WQA + sel) * 65536 + j * 256 + i] = __float2bfloat16_rn(s);
    } else {
        float s = ab1[j];
        for (int d = 0; d < 256; ++d)
            s = fmaf(pb2[d], aw1[d * 256 + j], s);
        g_bpa[j] = s;
    }
}

__global__ __launch_bounds__(256)
void conv_x_kernel(const float* __restrict__ x)
{
    const int i4 = blockIdx.x * 256 + threadIdx.x;   // float4 index
    if (i4 < BNP * DIMV / 4) {
        float4 v = *(const float4*)(x + (size_t)i4 * 4);
        bf162* o = (bf162*)(g_xb + (size_t)i4 * 4);
        o[0] = __floats2bfloat162_rn(v.x, v.y);
        o[1] = __floats2bfloat162_rn(v.z, v.w);
    }
}

// -------------------- KNN: warp-collective threshold top-16 --------------------
__device__ __forceinline__ bool dless(float d1, int i1, float d2, int i2) {
    return (d1 < d2) || (d1 == d2 && i1 < i2);
}

#define KNN_SMEM_BYTES (4 * NN * 4)

__global__ __launch_bounds__(256)
void knn_kernel(const float* __restrict__ pos)
{
    extern __shared__ float sm[];
    float* px = sm;
    float* py = sm + NN;
    float* pz = sm + 2 * NN;
    float* sj = sm + 3 * NN;

    const int b = blockIdx.x >> 9;             // 512 blocks per batch
    const float* pb = pos + (size_t)b * NN * 3;
    for (int j = threadIdx.x; j < NN; j += 256) {
        float x = pb[3 * j], y = pb[3 * j + 1], z = pb[3 * j + 2];
        px[j] = x; py[j] = y; pz[j] = z;
        sj[j] = x * x + y * y + z * z;
    }
    __syncthreads();

    const int warp = threadIdx.x >> 5, lane = threadIdx.x & 31;
    const int q  = blockIdx.x * 8 + warp;       // global query
    const int ql = q & (NN - 1);
    const float qx = px[ql], qy = py[ql], qz = pz[ql];
    const float qsq = sj[ql];

    const unsigned FULL = 0xffffffffu;
    float ld  = 3.4e38f; int li   = 0x7fffffff;
    float tau = 3.4e38f; int taui = 0x7fffffff;

#define KNN_INSERT(cd, cj)                                             \
    {                                                                  \
        bool keep = dless(ld, li, (cd), (cj));                         \
        unsigned bal = __ballot_sync(FULL, keep) & 0xffffu;            \
        int p = __popc(bal);                                           \
        float pd = __shfl_up_sync(FULL, ld, 1);                        \
        int   pi = __shfl_up_sync(FULL, li, 1);                        \
        if (lane == p) { ld = (cd); li = (cj); }                       \
        else if (lane > p && lane < 16) { ld = pd; li = pi; }          \
        tau  = __shfl_sync(FULL, ld, 15);                              \
        taui = __shfl_sync(FULL, li, 15);                              \
    }

#define KNN_HANDLE(dd, jj)                                             \
    {                                                                  \
        unsigned any = __ballot_sync(FULL, dless(dd, jj, tau, taui));  \
        while (any) {                                                  \
            int src = __ffs(any) - 1; any &= any - 1;                  \
            float cd = __shfl_sync(FULL, dd, src);                     \
            int   cj = __shfl_sync(FULL, jj, src);                     \
            if (dless(cd, cj, tau, taui)) KNN_INSERT(cd, cj);          \
        }                                                              \
    }

    for (int base = 0; base < NN; base += 128) {
        const int j0 = base + lane;
        const int j1 = j0 + 32;
        const int j2 = j0 + 64;
        const int j3 = j0 + 96;
        float d0 = qsq + sj[j0] - 2.f * (qx * px[j0] + qy * py[j0] + qz * pz[j0]);
        float d1 = qsq + sj[j1] - 2.f * (qx * px[j1] + qy * py[j1] + qz * pz[j1]);
        float d2 = qsq + sj[j2] - 2.f * (qx * px[j2] + qy * py[j2] + qz * pz[j2]);
        float d3 = qsq + sj[j3] - 2.f * (qx * px[j3] + qy * py[j3] + qz * pz[j3]);
        KNN_HANDLE(d0, j0)
        KNN_HANDLE(d1, j1)
        KNN_HANDLE(d2, j2)
        KNN_HANDLE(d3, j3)
    }

    if (lane < KNNV) g_idx[q * KNNV + lane] = b * NN + li;
#undef KNN_INSERT
#undef KNN_HANDLE
}

// ---------- h = relu(rel @ pw1 + pb1), rel = pos[n] - pos[neigh] ----------
__global__ __launch_bounds__(256)
void build_h_kernel(const float* __restrict__ pos, const float* __restrict__ pw1,
                    const float* __restrict__ pb1)
{
    const int m = blockIdx.x;          // 0..M2-1
    const int d = threadIdx.x;
    const int n = m >> 4;              // global query row
    const int r = g_idx[m];            // global neighbor row
    const float rx = pos[3 * n]     - pos[3 * r];
    const float ry = pos[3 * n + 1] - pos[3 * r + 1];
    const float rz = pos[3 * n + 2] - pos[3 * r + 2];
    float v = pb1[d] + rx * pw1[d] + ry * pw1[DIMV + d] + rz * pw1[2 * DIMV + d];
    g_h[(size_t)m * DIMV + d] = __float2bfloat16_rn(fmaxf(v, 0.f));
}

// ---------- softmax over K (per channel) + weighted aggregate ----------
__global__ __launch_bounds__(256)
void softmax_agg_kernel()
{
    const int n = blockIdx.x;          // 0..8191
    const int d = threadIdx.x;
    const float inv_scale = 1.0f / 16.0f;   // 1/sqrt(256)

    float a[KNNV];
    float mx = -3.4e38f;
#pragma unroll
    for (int kk = 0; kk < KNNV; ++kk) {
        a[kk] = __bfloat162float(g_a2[((size_t)(n * KNNV + kk)) * DIMV + d]) * inv_scale;
        mx = fmaxf(mx, a[kk]);
    }
    float s = 0.f;
#pragma unroll
    for (int kk = 0; kk < KNNV; ++kk) {
        float e = expf(a[kk] - mx);
        a[kk] = e;
        s += e;
    }
    const float invs = 1.f / s;
    float acc = 0.f;
#pragma unroll
    for (int kk = 0; kk < KNNV; ++kk) {
        int r = g_idx[n * KNNV + kk];
        acc += a[kk] * (__bfloat162float(g_v[(size_t)r * DIMV + d]) +
                        __bfloat162float(g_pe[((size_t)(n * KNNV + kk)) * DIMV + d]));
    }
    g_agg[(size_t)n * DIMV + d] = __float2bfloat16_rn(acc * invs);
}

// -------------------- launch --------------------
extern "C" void kernel_launch(void* const* d_in, const int* in_sizes, int n_in,
                              void* d_out, int out_size)
{
    const float* x   = (const float*)d_in[0];
    const float* pos = (const float*)d_in[1];
    const float* wq  = (const float*)d_in[2];
    const float* wk  = (const float*)d_in[3];
    const float* wv  = (const float*)d_in[4];
    const float* pw1 = (const float*)d_in[5];
    const float* pb1 = (const float*)d_in[6];
    const float* pw2 = (const float*)d_in[7];
    const float* pb2 = (const float*)d_in[8];
    const float* aw1 = (const float*)d_in[9];
    const float* ab1 = (const float*)d_in[10];
    const float* aw2 = (const float*)d_in[11];
    const float* ab2 = (const float*)d_in[12];
    const float* fw  = (const float*)d_in[13];
    const float* fb  = (const float*)d_in[14];
    (void)in_sizes; (void)n_in; (void)out_size;

    float *qa, *ka, *bpa;
    bf16 *v, *agg, *h, *pe, *h2, *a2, *wt, *xb;
    cudaGetSymbolAddress((void**)&qa,  g_qa);
    cudaGetSymbolAddress((void**)&ka,  g_ka);
    cudaGetSymbolAddress((void**)&v,   g_v);
    cudaGetSymbolAddress((void**)&agg, g_agg);
    cudaGetSymbolAddress((void**)&h,   g_h);
    cudaGetSymbolAddress((void**)&pe,  g_pe);
    cudaGetSymbolAddress((void**)&h2,  g_h2);
    cudaGetSymbolAddress((void**)&a2,  g_a2);
    cudaGetSymbolAddress((void**)&wt,  g_wt);
    cudaGetSymbolAddress((void**)&xb,  g_xb);
    cudaGetSymbolAddress((void**)&bpa, g_bpa);

    cudaFuncSetAttribute(gemm_bf16_kernel,
                         cudaFuncAttributeMaxDynamicSharedMemorySize, GEMM_SMEM_BYTES);
    cudaFuncSetAttribute(knn_kernel,
                         cudaFuncAttributeMaxDynamicSharedMemorySize, KNN_SMEM_BYTES);

    const bf16* wvt  = wt + (size_t)WT_WV  * 65536;
    const bf16* pw2t = wt + (size_t)WT_PW2 * 65536;
    const bf16* aw2t = wt + (size_t)WT_AW2 * 65536;
    const bf16* fwt  = wt + (size_t)WT_FW  * 65536;
    const bf16* wqat = wt + (size_t)WT_WQA * 65536;
    const bf16* wkat = wt + (size_t)WT_WKA * 65536;
    const bf16* wpat = wt + (size_t)WT_WPA * 65536;

    dim3 blk(256);

    // prep
    WSrcs ws; ws.p[0] = wv; ws.p[1] = pw2; ws.p[2] = aw2; ws.p[3] = fw;
    conv_weights_kernel<<<1024, blk>>>(ws);
    fold_kernel<<<769, blk>>>(wq, wk, pw2, aw1, pb2, ab1);
    conv_x_kernel<<<BNP * DIMV / 4 / 256, blk>>>(x);

    // qa & ka (dual, fp32 out)
    gemm_bf16_kernel<<<dim3(4, BNP / 128), blk, GEMM_SMEM_BYTES>>>(
        xb, wqat, wkat, nullptr, nullptr, nullptr, nullptr, nullptr,
        qa, ka, BNP, 0, 0);

    // v (bf16 out)
    gemm_bf16_kernel<<<dim3(2, BNP / 128), blk, GEMM_SMEM_BYTES>>>(
        xb, wvt, nullptr, nullptr, nullptr, nullptr, nullptr, nullptr,
        v, nullptr, BNP, F_OBF, 0);

    // knn
    knn_kernel<<<BNP / 8, blk, KNN_SMEM_BYTES>>>(pos);

    // h = relu(rel@pw1+pb1)
    build_h_kernel<<<M2, blk>>>(pos, pw1, pb1);

    // pe = h@pw2 + pb2  AND  h2 = relu(h@Wpa + bpa + qa[n] - ka[r])  (dual)
    gemm_bf16_kernel<<<dim3(4, M2 / 128), blk, GEMM_SMEM_BYTES>>>(
        h, pw2t, wpat, pb2, bpa, qa, ka, nullptr,
        pe, h2, M2, F_OBF, F_OBF | F_RELU | F_QK);

    // a2 = h2@aw2 + ab2
    gemm_bf16_kernel<<<dim3(2, M2 / 128), blk, GEMM_SMEM_BYTES>>>(
        h2, aw2t, nullptr, ab2, nullptr, nullptr, nullptr, nullptr,
        a2, nullptr, M2, F_OBF, 0);

    // softmax over K + aggregate
    softmax_agg_kernel<<<BNP, blk>>>();

    // out = agg@fw + fb + x
    gemm_bf16_kernel<<<dim3(2, BNP / 128), blk, GEMM_SMEM_BYTES>>>(
        agg, fwt, nullptr, fb, nullptr, nullptr, nullptr, x,
        (float*)d_out, nullptr, BNP, 0, 0);
}

// round 7
// speedup vs baseline: 1.1104x; 1.1104x over previous
#include <cuda_runtime.h>
#include <cuda_bf16.h>
#include <math.h>
#include <stdint.h>

// Problem constants
#define BB   2
#define NN   4096
#define BNP  (BB*NN)        // 8192 rows
#define DIMV 256
#define KNNV 16
#define M2   (BNP*KNNV)     // 131072 rows for per-neighbor tensors

typedef __nv_bfloat16 bf16;
typedef __nv_bfloat162 bf162;

// -------------------- scratch (no allocations allowed) --------------------
__device__ float g_qa [BNP*DIMV];          // x @ (wq@aw1)
__device__ float g_ka [BNP*DIMV];          // x @ (wk@aw1)
__device__ bf16  g_v  [BNP*DIMV];
__device__ bf16  g_agg[BNP*DIMV];
__device__ int   g_idx[M2];
__device__ bf16  g_h  [(size_t)M2*DIMV];   // relu(rel@pw1+pb1)
__device__ bf16  g_pe [(size_t)M2*DIMV];   // h@pw2+pb2
__device__ bf16  g_h2 [(size_t)M2*DIMV];   // relu(h@Wpa + qa - ka + bpa)
__device__ bf16  g_wt [7*DIMV*DIMV];       // transposed bf16 weights [n][k]
__device__ bf16  g_xb [BNP*DIMV];          // bf16 x
__device__ float g_bpa[DIMV];              // pb2@aw1 + ab1

// weight slots in g_wt
#define WT_WV  0
#define WT_PW2 1
#define WT_AW2 2
#define WT_FW  3
#define WT_WQA 4
#define WT_WKA 5
#define WT_WPA 6

// ==================== bf16 tensor-core GEMM ====================
// CTA tile 128x128, BK=64, 8 warps (2x4), mma.m16n8k16.bf16, ldmatrix frags.
// A: M x 256 bf16 row-major.  Bt: 256 x 256 bf16 TRANSPOSED [n][k].
// Dual mode: grid.x=4, CTAs 0-1 use (Bt0,...), 2-3 use (Bt1,...).

#define BKV   64
#define ASTR  72                    // bf16 elems per smem row (144B)
#define TBUF  (128*ASTR)            // one tile buffer (bf16 elems)
#define GEMM_SMEM_BYTES (4*TBUF*2)  // A x2 + B x2 = 73728 B
#define RSTR  132                   // staging stride (floats); 128*132*4 = 67584 B

// epilogue flags
#define F_RELU    1
#define F_OBF     2
#define F_QK      4
#define F_SOFTAGG 8

__device__ __forceinline__ void cp16b(bf16* s, const bf16* g) {
    uint32_t sa = (uint32_t)__cvta_generic_to_shared(s);
    asm volatile("cp.async.cg.shared.global [%0], [%1], 16;\n" :: "r"(sa), "l"(g));
}

#define LDSM4(r0, r1, r2, r3, addr)                                          \
    asm volatile("ldmatrix.sync.aligned.m8n8.x4.shared.b16 {%0,%1,%2,%3}, [%4];" \
                 : "=r"(r0), "=r"(r1), "=r"(r2), "=r"(r3) : "r"(addr))

__global__ __launch_bounds__(256)
void gemm_bf16_kernel(const bf16* __restrict__ A,
                      const bf16* __restrict__ Bt0, const bf16* __restrict__ Bt1,
                      const float* __restrict__ bias0, const float* __restrict__ bias1,
                      const float* __restrict__ qa, const float* __restrict__ ka,
                      const float* __restrict__ resid,
                      void* __restrict__ out0, void* __restrict__ out1,
                      int M, int flags0, int flags1)
{
    extern __shared__ bf16 smem[];
    bf16* As = smem;              // [2][128][ASTR]
    bf16* Bs = smem + 2 * TBUF;   // [2][128][ASTR]

    const int tid  = threadIdx.x;
    const int lane = tid & 31;
    const int warp = tid >> 5;
    const int wm   = warp >> 2;       // 0..1  -> 64 rows
    const int wn   = warp & 3;        // 0..3  -> 32 cols
    const int bm   = blockIdx.y * 128;

    int sub, bn;
    if (Bt1) { sub = blockIdx.x >> 1; bn = (blockIdx.x & 1) * 128; }
    else     { sub = 0;               bn = blockIdx.x * 128; }
    const bf16*  Bt    = sub ? Bt1    : Bt0;
    const float* bias  = sub ? bias1  : bias0;
    void*        Cout  = sub ? out1   : out0;
    const int    flags = sub ? flags1 : flags0;

    const int g  = lane >> 2;         // groupID 0..7
    const int tg = lane & 3;          // thread-in-group 0..3

    float acc[4][4][4];
#pragma unroll
    for (int i = 0; i < 4; ++i)
#pragma unroll
        for (int j = 0; j < 4; ++j)
#pragma unroll
            for (int c = 0; c < 4; ++c) acc[i][j][c] = 0.f;

    auto load_tile = [&](int buf, int k0) {
#pragma unroll
        for (int u = 0; u < 4; ++u) {
            int idx = tid + u * 256;          // 0..1023
            int row = idx >> 3;               // 0..127
            int c8  = (idx & 7) * 8;          // 0..56 (bf16 elems)
            cp16b(&As[buf * TBUF + row * ASTR + c8],
                  A + (size_t)(bm + row) * 256 + k0 + c8);
        }
#pragma unroll
        for (int u = 0; u < 4; ++u) {
            int idx = tid + u * 256;
            int row = idx >> 3;               // n index 0..127
            int c8  = (idx & 7) * 8;
            cp16b(&Bs[buf * TBUF + row * ASTR + c8],
                  Bt + (size_t)(bn + row) * 256 + k0 + c8);
        }
        asm volatile("cp.async.commit_group;\n");
    };

    // ldmatrix per-lane base addresses
    const int sel  = lane >> 3;       // 0..3
    const int rsub = lane & 7;
    const uint32_t sA = (uint32_t)__cvta_generic_to_shared(As);
    const uint32_t sB = (uint32_t)__cvta_generic_to_shared(Bs);
    const uint32_t aBase =
        sA + (uint32_t)(((wm * 64 + rsub + (sel & 1) * 8) * ASTR + (sel >> 1) * 8) * 2);
    const uint32_t bBase =
        sB + (uint32_t)(((wn * 32 + rsub + (sel & 1) * 8) * ASTR + (sel >> 1) * 8) * 2);

    load_tile(0, 0);

    for (int t = 0; t < 4; ++t) {
        const int buf = t & 1;
        if (t < 3) {
            load_tile(buf ^ 1, (t + 1) * BKV);
            asm volatile("cp.async.wait_group 1;\n");
        } else {
            asm volatile("cp.async.wait_group 0;\n");
        }
        __syncthreads();

        const uint32_t aT = aBase + (uint32_t)buf * (TBUF * 2);
        const uint32_t bT = bBase + (uint32_t)buf * (TBUF * 2);

#pragma unroll
        for (int ks = 0; ks < 4; ++ks) {
            const uint32_t koff = ks * 16 * 2;
            uint32_t af[4][4], bfr[4][2];
#pragma unroll
            for (int mt = 0; mt < 4; ++mt) {
                LDSM4(af[mt][0], af[mt][1], af[mt][2], af[mt][3],
                      aT + (uint32_t)(mt * 16 * ASTR * 2) + koff);
            }
#pragma unroll
            for (int p = 0; p < 2; ++p) {
                LDSM4(bfr[2 * p][0], bfr[2 * p + 1][0], bfr[2 * p][1], bfr[2 * p + 1][1],
                      bT + (uint32_t)(p * 16 * ASTR * 2) + koff);
            }
#pragma unroll
            for (int mt = 0; mt < 4; ++mt)
#pragma unroll
                for (int nt = 0; nt < 4; ++nt) {
                    asm volatile(
                        "mma.sync.aligned.m16n8k16.row.col.f32.bf16.bf16.f32 "
                        "{%0,%1,%2,%3}, {%4,%5,%6,%7}, {%8,%9}, {%0,%1,%2,%3};\n"
                        : "+f"(acc[mt][nt][0]), "+f"(acc[mt][nt][1]),
                          "+f"(acc[mt][nt][2]), "+f"(acc[mt][nt][3])
                        : "r"(af[mt][0]), "r"(af[mt][1]), "r"(af[mt][2]), "r"(af[mt][3]),
                          "r"(bfr[nt][0]), "r"(bfr[nt][1]));
                }
        }
        __syncthreads();
    }

    // ==================== epilogues ====================
    if (flags & F_SOFTAGG) {
        // Stage the 128x128 tile in smem (8 queries x 16 neighbors x 128 ch),
        // then per-(query, channel) serial softmax over K + aggregate.
        float* sred = (float*)smem;                 // [128][RSTR]
        const float inv_scale = 1.0f / 16.0f;       // 1/sqrt(256)
#pragma unroll
        for (int mt = 0; mt < 4; ++mt)
#pragma unroll
            for (int nt = 0; nt < 4; ++nt) {
                int rl = wm * 64 + mt * 16 + g;
                int cl = wn * 32 + nt * 8 + 2 * tg;
                sred[rl * RSTR + cl]           = (acc[mt][nt][0] + bias[bn + cl])     * inv_scale;
                sred[rl * RSTR + cl + 1]       = (acc[mt][nt][1] + bias[bn + cl + 1]) * inv_scale;
                sred[(rl + 8) * RSTR + cl]     = (acc[mt][nt][2] + bias[bn + cl])     * inv_scale;
                sred[(rl + 8) * RSTR + cl + 1] = (acc[mt][nt][3] + bias[bn + cl + 1]) * inv_scale;
            }
        __syncthreads();
#pragma unroll
        for (int i = 0; i < 4; ++i) {
            const int p  = tid + i * 256;     // 0..1023
            const int q  = p >> 7;            // local query 0..7
            const int c  = p & 127;           // local channel
            const int m0 = bm + q * 16;       // global row of neighbor k=0
            float vals[KNNV];
            float mx = -3.4e38f;
#pragma unroll
            for (int k = 0; k < KNNV; ++k) {
                vals[k] = sred[(q * 16 + k) * RSTR + c];
                mx = fmaxf(mx, vals[k]);
            }
            float s = 0.f, accv = 0.f;
#pragma unroll
            for (int k = 0; k < KNNV; ++k) {
                float e = __expf(vals[k] - mx);
                int r = g_idx[m0 + k];
                float pv = __bfloat162float(g_pe[(size_t)(m0 + k) * 256 + bn + c])
                         + __bfloat162float(g_v [(size_t)r * 256 + bn + c]);
                s += e;
                accv = fmaf(e, pv, accv);
            }
            const int qg = m0 >> 4;           // global query row
            ((bf16*)Cout)[(size_t)qg * 256 + bn + c] = __float2bfloat16_rn(accv / s);
        }
        return;
    }

    const bool doRelu = flags & F_RELU;
    const bool obf    = flags & F_OBF;
    const bool doQK   = flags & F_QK;
#pragma unroll
    for (int mt = 0; mt < 4; ++mt) {
#pragma unroll
        for (int nt = 0; nt < 4; ++nt) {
            int row0 = bm + wm * 64 + mt * 16 + g;
            int col0 = bn + wn * 32 + nt * 8 + 2 * tg;
#pragma unroll
            for (int h = 0; h < 2; ++h) {
                int row = row0 + h * 8;
                float c0 = acc[mt][nt][2 * h];
                float c1 = acc[mt][nt][2 * h + 1];
                if (bias) { c0 += bias[col0]; c1 += bias[col0 + 1]; }
                if (doQK) {
                    int n = row >> 4;
                    int r = g_idx[row];
                    float2 qv = *(const float2*)(qa + (size_t)n * 256 + col0);
                    float2 kv = *(const float2*)(ka + (size_t)r * 256 + col0);
                    c0 += qv.x - kv.x;
                    c1 += qv.y - kv.y;
                }
                if (doRelu) { c0 = fmaxf(c0, 0.f); c1 = fmaxf(c1, 0.f); }
                if (obf) {
                    *(bf162*)((bf16*)Cout + (size_t)row * 256 + col0) =
                        __floats2bfloat162_rn(c0, c1);
                } else {
                    if (resid) {
                        c0 += resid[(size_t)row * 256 + col0];
                        c1 += resid[(size_t)row * 256 + col0 + 1];
                    }
                    *(float2*)((float*)Cout + (size_t)row * 256 + col0) =
                        make_float2(c0, c1);
                }
            }
        }
    }
}

// -------------------- prep: convert / transpose / fold --------------------
struct WSrcs { const float* p[4]; };   // wv, pw2, aw2, fw

__global__ __launch_bounds__(256)
void conv_weights_kernel(WSrcs ws)
{
    const int sel = blockIdx.x >> 8;      // 0..3
    const int n   = blockIdx.x & 255;
    const int k   = threadIdx.x;
    g_wt[(size_t)sel * 65536 + n * 256 + k] =
        __float2bfloat16_rn(ws.p[sel][k * 256 + n]);
}

// Wqa = wq@aw1, Wka = wk@aw1, Wpa = pw2@aw1 (stored transposed, bf16),
// bpa = pb2@aw1 + ab1 (fp32)
__global__ __launch_bounds__(256)
void fold_kernel(const float* __restrict__ wq, const float* __restrict__ wk,
                 const float* __restrict__ pw2, const float* __restrict__ aw1,
                 const float* __restrict__ pb2, const float* __restrict__ ab1)
{
    const int b = blockIdx.x;
    const int j = threadIdx.x;
    if (b < 768) {
        const int sel = b >> 8;
        const int i   = b & 255;
        const float* src = (sel == 0) ? wq : (sel == 1) ? wk : pw2;
        float s = 0.f;
        for (int d = 0; d < 256; ++d)
            s = fmaf(src[i * 256 + d], aw1[d * 256 + j], s);
        g_wt[(size_t)(WT_WQA + sel) * 65536 + j * 256 + i] = __float2bfloat16_rn(s);
    } else {
        float s = ab1[j];
        for (int d = 0; d < 256; ++d)
            s = fmaf(pb2[d], aw1[d * 256 + j], s);
        g_bpa[j] = s;
    }
}

__global__ __launch_bounds__(256)
void conv_x_kernel(const float* __restrict__ x)
{
    const int i4 = blockIdx.x * 256 + threadIdx.x;   // float4 index
    if (i4 < BNP * DIMV / 4) {
        float4 v = *(const float4*)(x + (size_t)i4 * 4);
        bf162* o = (bf162*)(g_xb + (size_t)i4 * 4);
        o[0] = __floats2bfloat162_rn(v.x, v.y);
        o[1] = __floats2bfloat162_rn(v.z, v.w);
    }
}

// -------------------- KNN: warp-collective threshold top-16 --------------------
__device__ __forceinline__ bool dless(float d1, int i1, float d2, int i2) {
    return (d1 < d2) || (d1 == d2 && i1 < i2);
}

#define KNN_SMEM_BYTES (4 * NN * 4)

__global__ __launch_bounds__(256)
void knn_kernel(const float* __restrict__ pos)
{
    extern __shared__ float sm[];
    float* px = sm;
    float* py = sm + NN;
    float* pz = sm + 2 * NN;
    float* sj = sm + 3 * NN;

    const int b = blockIdx.x >> 9;             // 512 blocks per batch
    const float* pb = pos + (size_t)b * NN * 3;
    for (int j = threadIdx.x; j < NN; j += 256) {
        float x = pb[3 * j], y = pb[3 * j + 1], z = pb[3 * j + 2];
        px[j] = x; py[j] = y; pz[j] = z;
        sj[j] = x * x + y * y + z * z;
    }
    __syncthreads();

    const int warp = threadIdx.x >> 5, lane = threadIdx.x & 31;
    const int q  = blockIdx.x * 8 + warp;       // global query
    const int ql = q & (NN - 1);
    const float qx = px[ql], qy = py[ql], qz = pz[ql];
    const float qsq = sj[ql];

    const unsigned FULL = 0xffffffffu;
    float ld  = 3.4e38f; int li   = 0x7fffffff;
    float tau = 3.4e38f; int taui = 0x7fffffff;

#define KNN_INSERT(cd, cj)                                             \
    {                                                                  \
        bool keep = dless(ld, li, (cd), (cj));                         \
        unsigned bal = __ballot_sync(FULL, keep) & 0xffffu;            \
        int p = __popc(bal);                                           \
        float pd = __shfl_up_sync(FULL, ld, 1);                        \
        int   pi = __shfl_up_sync(FULL, li, 1);                        \
        if (lane == p) { ld = (cd); li = (cj); }                       \
        else if (lane > p && lane < 16) { ld = pd; li = pi; }          \
        tau  = __shfl_sync(FULL, ld, 15);                              \
        taui = __shfl_sync(FULL, li, 15);                              \
    }

#define KNN_HANDLE(dd, jj)                                             \
    {                                                                  \
        unsigned any = __ballot_sync(FULL, dless(dd, jj, tau, taui));  \
        while (any) {                                                  \
            int src = __ffs(any) - 1; any &= any - 1;                  \
            float cd = __shfl_sync(FULL, dd, src);                     \
            int   cj = __shfl_sync(FULL, jj, src);                     \
            if (dless(cd, cj, tau, taui)) KNN_INSERT(cd, cj);          \
        }                                                              \
    }

    for (int base = 0; base < NN; base += 128) {
        const int j0 = base + lane;
        const int j1 = j0 + 32;
        const int j2 = j0 + 64;
        const int j3 = j0 + 96;
        float d0 = qsq + sj[j0] - 2.f * (qx * px[j0] + qy * py[j0] + qz * pz[j0]);
        float d1 = qsq + sj[j1] - 2.f * (qx * px[j1] + qy * py[j1] + qz * pz[j1]);
        float d2 = qsq + sj[j2] - 2.f * (qx * px[j2] + qy * py[j2] + qz * pz[j2]);
        float d3 = qsq + sj[j3] - 2.f * (qx * px[j3] + qy * py[j3] + qz * pz[j3]);
        KNN_HANDLE(d0, j0)
        KNN_HANDLE(d1, j1)
        KNN_HANDLE(d2, j2)
        KNN_HANDLE(d3, j3)
    }

    if (lane < KNNV) g_idx[q * KNNV + lane] = b * NN + li;
#undef KNN_INSERT
#undef KNN_HANDLE
}

// ---------- h = relu(rel @ pw1 + pb1), rel = pos[n] - pos[neigh] ----------
// grid M2/2, block 256: 2 rows per block, 2 channels per thread.
__global__ __launch_bounds__(256)
void build_h_kernel(const float* __restrict__ pos, const float* __restrict__ pw1,
                    const float* __restrict__ pb1)
{
    const int m = blockIdx.x * 2 + (threadIdx.x >> 7);
    const int d = (threadIdx.x & 127) * 2;
    const int n = m >> 4;              // global query row
    const int r = g_idx[m];            // global neighbor row
    const float rx = pos[3 * n]     - pos[3 * r];
    const float ry = pos[3 * n + 1] - pos[3 * r + 1];
    const float rz = pos[3 * n + 2] - pos[3 * r + 2];
    float v0 = pb1[d]   + rx * pw1[d]     + ry * pw1[DIMV + d]     + rz * pw1[2 * DIMV + d];
    float v1 = pb1[d+1] + rx * pw1[d + 1] + ry * pw1[DIMV + d + 1] + rz * pw1[2 * DIMV + d + 1];
    *(bf162*)(g_h + (size_t)m * DIMV + d) =
        __floats2bfloat162_rn(fmaxf(v0, 0.f), fmaxf(v1, 0.f));
}

// -------------------- launch --------------------
extern "C" void kernel_launch(void* const* d_in, const int* in_sizes, int n_in,
                              void* d_out, int out_size)
{
    const float* x   = (const float*)d_in[0];
    const float* pos = (const float*)d_in[1];
    const float* wq  = (const float*)d_in[2];
    const float* wk  = (const float*)d_in[3];
    const float* wv  = (const float*)d_in[4];
    const float* pw1 = (const float*)d_in[5];
    const float* pb1 = (const float*)d_in[6];
    const float* pw2 = (const float*)d_in[7];
    const float* pb2 = (const float*)d_in[8];
    const float* aw1 = (const float*)d_in[9];
    const float* ab1 = (const float*)d_in[10];
    const float* aw2 = (const float*)d_in[11];
    const float* ab2 = (const float*)d_in[12];
    const float* fw  = (const float*)d_in[13];
    const float* fb  = (const float*)d_in[14];
    (void)in_sizes; (void)n_in; (void)out_size;

    float *qa, *ka, *bpa;
    bf16 *v, *agg, *h, *pe, *h2, *wt, *xb;
    cudaGetSymbolAddress((void**)&qa,  g_qa);
    cudaGetSymbolAddress((void**)&ka,  g_ka);
    cudaGetSymbolAddress((void**)&v,   g_v);
    cudaGetSymbolAddress((void**)&agg, g_agg);
    cudaGetSymbolAddress((void**)&h,   g_h);
    cudaGetSymbolAddress((void**)&pe,  g_pe);
    cudaGetSymbolAddress((void**)&h2,  g_h2);
    cudaGetSymbolAddress((void**)&wt,  g_wt);
    cudaGetSymbolAddress((void**)&xb,  g_xb);
    cudaGetSymbolAddress((void**)&bpa, g_bpa);

    cudaFuncSetAttribute(gemm_bf16_kernel,
                         cudaFuncAttributeMaxDynamicSharedMemorySize, GEMM_SMEM_BYTES);
    cudaFuncSetAttribute(knn_kernel,
                         cudaFuncAttributeMaxDynamicSharedMemorySize, KNN_SMEM_BYTES);

    const bf16* wvt  = wt + (size_t)WT_WV  * 65536;
    const bf16* pw2t = wt + (size_t)WT_PW2 * 65536;
    const bf16* aw2t = wt + (size_t)WT_AW2 * 65536;
    const bf16* fwt  = wt + (size_t)WT_FW  * 65536;
    const bf16* wqat = wt + (size_t)WT_WQA * 65536;
    const bf16* wkat = wt + (size_t)WT_WKA * 65536;
    const bf16* wpat = wt + (size_t)WT_WPA * 65536;

    dim3 blk(256);

    // prep
    WSrcs ws; ws.p[0] = wv; ws.p[1] = pw2; ws.p[2] = aw2; ws.p[3] = fw;
    conv_weights_kernel<<<1024, blk>>>(ws);
    fold_kernel<<<769, blk>>>(wq, wk, pw2, aw1, pb2, ab1);
    conv_x_kernel<<<BNP * DIMV / 4 / 256, blk>>>(x);

    // qa & ka (dual, fp32 out)
    gemm_bf16_kernel<<<dim3(4, BNP / 128), blk, GEMM_SMEM_BYTES>>>(
        xb, wqat, wkat, nullptr, nullptr, nullptr, nullptr, nullptr,
        qa, ka, BNP, 0, 0);

    // v (bf16 out)
    gemm_bf16_kernel<<<dim3(2, BNP / 128), blk, GEMM_SMEM_BYTES>>>(
        xb, wvt, nullptr, nullptr, nullptr, nullptr, nullptr, nullptr,
        v, nullptr, BNP, F_OBF, 0);

    // knn
    knn_kernel<<<BNP / 8, blk, KNN_SMEM_BYTES>>>(pos);

    // h = relu(rel@pw1+pb1)
    build_h_kernel<<<M2 / 2, blk>>>(pos, pw1, pb1);

    // pe = h@pw2 + pb2  AND  h2 = relu(h@Wpa + bpa + qa[n] - ka[r])  (dual)
    gemm_bf16_kernel<<<dim3(4, M2 / 128), blk, GEMM_SMEM_BYTES>>>(
        h, pw2t, wpat, pb2, bpa, qa, ka, nullptr,
        pe, h2, M2, F_OBF, F_OBF | F_RELU | F_QK);

    // agg = softmax_K((h2@aw2 + ab2)/16) . (v[idx] + pe)  — fused, smem-staged
    gemm_bf16_kernel<<<dim3(2, M2 / 128), blk, GEMM_SMEM_BYTES>>>(
        h2, aw2t, nullptr, ab2, nullptr, nullptr, nullptr, nullptr,
        agg, nullptr, M2, F_SOFTAGG, 0);

    // out = agg@fw + fb + x
    gemm_bf16_kernel<<<dim3(2, BNP / 128), blk, GEMM_SMEM_BYTES>>>(
        agg, fwt, nullptr, fb, nullptr, nullptr, nullptr, x,
        (float*)d_out, nullptr, BNP, 0, 0);
}